// round 14
// baseline (speedup 1.0000x reference)
#include <cuda_runtime.h>
#include <math.h>

#define NIMG 4
#define CC 15
#define KLOC 65536            // H*W
#define KC (KLOC*CC)          // 983040
#define TOPK 400
#define POSTN 100
#define NBINS 2048            // fine bins over [0.25, 1): (bits-FLOOR)>>13
#define BIN_SHIFT 13
#define CAP 16384
#define SPILLCAP 262144
#define NWORDS 13             // ceil(400/32)
#define FLOOR_BITS 0x3E800000u    // 0.25f
#define SCREEN_SUM (-1e-3f)       // x+y >= 0 is necessary for sig(x)*sig(y) >= 0.25

// ---------------- scratch (device globals; zero-initialized at load; kernels
// restore them to zero each iteration, so graph replays are deterministic) ----
__device__ unsigned int       g_hist[NIMG*NBINS];
__device__ int                g_scnt[NIMG];
__device__ unsigned long long g_spill[(size_t)NIMG*SPILLCAP];
__device__ unsigned long long g_top[NIMG*TOPK];
__device__ float              g_corners[NIMG*TOPK*8];
__device__ float4             g_meta[NIMG*TOPK];     // cx, cy, radius, area
__device__ float4             g_pack[NIMG*TOPK];     // cx, cy, radius, label (0 = invalid)
__device__ float              g_score[NIMG*TOPK];
__device__ int                g_label[NIMG*TOPK];    // 0 when invalid
__device__ unsigned int       g_sup[NIMG*TOPK*NWORDS];

__device__ __forceinline__ float sigmoidf_(float x){ return 1.0f/(1.0f+expf(-x)); }

// ---------------- K1: single pass over box_cls (AM-GM sum screen, no ballots) ----------------
__global__ void __launch_bounds__(256) kPass(const float* __restrict__ cls,
                                             const float* __restrict__ ctr) {
    __shared__ unsigned int       sh[NBINS];        // 8 KB
    __shared__ unsigned long long s_buf[4096];      // 32 KB (worst-case = block capacity)
    __shared__ int s_cnt, s_base;
    for (int i = threadIdx.x; i < NBINS; i += blockDim.x) sh[i] = 0u;
    if (threadIdx.x == 0) s_cnt = 0;
    __syncthreads();
    int n = blockIdx.y;
    const float4* base = (const float4*)(cls + (size_t)n*KC);
    const float*  ctrb = ctr + n*KLOC;        // raw logits; L2-hot (reused 15x)
    int v0 = blockIdx.x*1024 + threadIdx.x;   // float4 index within image
    #pragma unroll
    for (int q = 0; q < 4; q++) {
        int v = v0 + q*256;
        float4 x4 = base[v];
        int e = v*4;
        int loc = e & (KLOC-1);
        int c   = e >> 16;                    // class index (4096-elem blocks never straddle)
        float4 y4 = *(const float4*)(ctrb + loc);
        float xs[4] = {x4.x, x4.y, x4.z, x4.w};
        float ys[4] = {y4.x, y4.y, y4.z, y4.w};
        #pragma unroll
        for (int j = 0; j < 4; j++) {
            // AM-GM: sig(x)*sig(y) >= 1/4  =>  x + y >= 0. Pure FADD+FCMP screen.
            if (xs[j] + ys[j] > SCREEN_SUM) {     // ~8% pass
                float comb = sigmoidf_(xs[j]) * sigmoidf_(ys[j]);
                unsigned int b = __float_as_uint(comb);
                if (b >= FLOOR_BITS) {            // exact verify (~4%)
                    atomicAdd(&sh[(b - FLOOR_BITS) >> BIN_SHIFT], 1u);
                    unsigned int flat = (unsigned int)(loc + j)*CC + (unsigned int)c;
                    int p = atomicAdd(&s_cnt, 1); // direct smem append
                    s_buf[p] = ((unsigned long long)b << 32) |
                               (unsigned long long)(0xFFFFFFFFu - flat);
                }
            }
        }
    }
    __syncthreads();
    for (int i = threadIdx.x; i < NBINS; i += blockDim.x)
        if (sh[i]) atomicAdd(&g_hist[n*NBINS + i], sh[i]);
    int cnt = s_cnt;
    if (threadIdx.x == 0 && cnt) s_base = atomicAdd(&g_scnt[n], cnt);
    __syncthreads();
    if (cnt) {
        int b0 = s_base;
        for (int i = threadIdx.x; i < cnt; i += blockDim.x) {
            int p = b0 + i;
            if (p < SPILLCAP) g_spill[(size_t)n*SPILLCAP + p] = s_buf[i];
        }
    }
}

// ---------------- K2: threshold bin (parallel), filter spill, bitonic sort, reset state ----------------
extern __shared__ unsigned long long s_keys[];
__global__ void __launch_bounds__(1024) kFilterSort() {
    __shared__ unsigned int s_gsum[64];
    __shared__ unsigned int s_thr;
    __shared__ int s_sel;
    int n = blockIdx.x, tid = threadIdx.x;    // 1024 threads
    int wid = tid >> 5, lane = tid & 31;

    if (wid < 32) {
        #pragma unroll
        for (int gi = 0; gi < 2; gi++) {
            int g = wid*2 + gi;
            unsigned int v = g_hist[n*NBINS + g*32 + lane];
            #pragma unroll
            for (int off = 16; off; off >>= 1) v += __shfl_xor_sync(0xffffffffu, v, off);
            if (lane == 0) s_gsum[g] = v;
        }
    }
    __syncthreads();
    if (tid == 0) {
        unsigned int run = 0, thr = FLOOR_BITS;
        int tg = -1;
        for (int g = 63; g >= 0; g--) {
            if (run + s_gsum[g] >= TOPK) { tg = g; break; }
            run += s_gsum[g];
        }
        if (tg >= 0) {
            for (int b = tg*32 + 31; b >= tg*32; b--) {
                run += g_hist[n*NBINS + b];
                if (run >= TOPK) { thr = FLOOR_BITS + ((unsigned int)b << BIN_SHIFT); break; }
            }
        }
        s_thr = thr; s_sel = 0;
    }
    __syncthreads();
    unsigned int thr = s_thr;
    int cnt = g_scnt[n]; if (cnt > SPILLCAP) cnt = SPILLCAP;
    const unsigned long long* sp = g_spill + (size_t)n*SPILLCAP;
    for (int i = tid; i < ((cnt + 31) & ~31); i += blockDim.x) {
        unsigned long long k = (i < cnt) ? sp[i] : 0ull;
        bool pass = (i < cnt) && ((unsigned int)(k >> 32) >= thr);
        unsigned int m = __ballot_sync(0xffffffffu, pass);
        if (m) {
            int leader = __ffs(m) - 1;
            int b0;
            if (lane == leader) b0 = atomicAdd(&s_sel, __popc(m));
            b0 = __shfl_sync(0xffffffffu, b0, leader);
            if (pass) {
                int p = b0 + __popc(m & ((1u << lane) - 1u));
                if (p < CAP) s_keys[p] = k;
            }
        }
    }
    __syncthreads();
    // reset per-image state for the next graph replay (reads above are done)
    for (int i = tid; i < NBINS; i += blockDim.x) g_hist[n*NBINS + i] = 0u;
    if (tid == 0) g_scnt[n] = 0;

    int sel = s_sel; if (sel > CAP) sel = CAP;
    int m = 512;
    while (m < sel) m <<= 1;
    for (int i = tid; i < m; i += blockDim.x)
        if (i >= sel) s_keys[i] = 0ull;
    __syncthreads();
    for (int k = 2; k <= m; k <<= 1) {
        for (int jj = k >> 1; jj > 0; jj >>= 1) {
            for (int i = tid; i < m; i += blockDim.x) {
                int l = i ^ jj;
                if (l > i) {
                    unsigned long long a = s_keys[i], b = s_keys[l];
                    bool desc = ((i & k) == 0);
                    if (desc ? (a < b) : (a > b)) { s_keys[i] = b; s_keys[l] = a; }
                }
            }
            __syncthreads();
        }
    }
    for (int i = tid; i < TOPK; i += blockDim.x)
        g_top[n*TOPK + i] = s_keys[i];   // m >= 512 > TOPK always
}

// ---------------- K3: decode boxes (2 warps = 64 threads per candidate) ----------------
__global__ void __launch_bounds__(256) kDecode(const float* __restrict__ angle,
                        const float* __restrict__ reg,
                        const float* __restrict__ anchors) {
    __shared__ float s_v[4][2];
    __shared__ int   s_i[4][2];
    int n = blockIdx.y;
    int sub = threadIdx.x >> 6;            // candidate within block (0..3)
    int st  = threadIdx.x & 63;            // 0..63
    int j = blockIdx.x*4 + sub;            // grid.x = 100 -> j in [0,400)
    unsigned long long key = g_top[n*TOPK + j];
    unsigned int bits = (unsigned int)(key >> 32);
    float topv = __uint_as_float(bits);
    bool valid = topv > 0.0f;
    unsigned int flat = 0xFFFFFFFFu - (unsigned int)(key & 0xFFFFFFFFull);
    int loc = valid ? (int)(flat / CC) : 0;
    int cls = valid ? (int)(flat % CC) : 0;

    float bv = -3.402823466e38f; int bi = 1 << 20;
    if (valid) {
        const float* ap = angle + (size_t)n*90*KLOC + loc;
        bv = __ldg(ap + (size_t)st*KLOC); bi = st;
        if (st + 64 < 90) {
            float v2 = __ldg(ap + (size_t)(st+64)*KLOC);
            if (v2 > bv) { bv = v2; bi = st + 64; }   // strict > keeps lower index
        }
    }
    #pragma unroll
    for (int off = 16; off; off >>= 1) {
        float ov = __shfl_xor_sync(0xffffffffu, bv, off);
        int   oi = __shfl_xor_sync(0xffffffffu, bi, off);
        if (ov > bv || (ov == bv && oi < bi)) { bv = ov; bi = oi; }
    }
    int wh = (threadIdx.x >> 5) & 1;
    if ((threadIdx.x & 31) == 0) { s_v[sub][wh] = bv; s_i[sub][wh] = bi; }
    __syncthreads();

    if (st == 0) {
        float v0 = s_v[sub][0], v1 = s_v[sub][1];
        int   i0 = s_i[sub][0], i1 = s_i[sub][1];
        if (v1 > v0 || (v1 == v0 && i1 < i0)) { v0 = v1; i0 = i1; }
        int base = n*TOPK + j;
        if (!valid) {
            g_label[base] = 0; g_score[base] = 0.f;
            g_meta[base] = make_float4(0.f, 0.f, 0.f, 0.f);
            g_pack[base] = make_float4(0.f, 0.f, 0.f, 0.f);
            #pragma unroll
            for (int q = 0; q < 8; q++) g_corners[base*8 + q] = 0.f;
            return;
        }
        const float* rp = reg + (size_t)n*4*KLOC + loc;
        float r0 = rp[0], r1 = rp[KLOC], r2 = rp[2*(size_t)KLOC], r3 = rp[3*(size_t)KLOC];
        const float* ap2 = anchors + ((size_t)n*KLOC + loc)*5;
        float acx = ap2[0], acy = ap2[1], aw = ap2[2], ah = ap2[3];
        float dx = r0/10.0f, dy = r1/10.0f;
        float dw = fminf(fmaxf(r2/5.0f, -10.0f), 4.0f);
        float dh = fminf(fmaxf(r3/5.0f, -10.0f), 4.0f);
        float cx = dx*aw + acx, cy = dy*ah + acy;
        float pw = aw*expf(dw), ph = ah*expf(dh);
        bool v2ok = (pw >= 0.0f) && (ph >= 0.0f);
        float ang = (float)i0 - 90.0f;
        float t = ang * 0.017453292519943295f;
        float c = cosf(t), s = sinf(t);
        const float oxm[4] = {1.f,-1.f,-1.f,1.f};
        const float oym[4] = {1.f, 1.f,-1.f,-1.f};
        #pragma unroll
        for (int q = 0; q < 4; q++) {
            float ox = oxm[q]*(pw*0.5f), oy = oym[q]*(ph*0.5f);
            g_corners[base*8 + 2*q]     = cx + ox*c - oy*s;
            g_corners[base*8 + 2*q + 1] = cy + ox*s + oy*c;
        }
        float rad = 0.5f*sqrtf(pw*pw + ph*ph) + 1.0f;
        int   lb  = v2ok ? (cls + 1) : 0;
        g_meta[base]  = make_float4(cx, cy, rad, pw*ph);
        g_pack[base]  = make_float4(cx, cy, rad, (float)lb);
        g_score[base] = v2ok ? sqrtf(fmaxf(topv, 0.f)) : 0.f;
        g_label[base] = lb;                             // 0 encodes invalid
    }
}

// ---------------- rotated quad intersection (mirrors reference Sutherland-Hodgman) ----------------
__device__ float quad_inter_area(const float* c1, const float* c2) {
    float px[16], py[16];
    #pragma unroll
    for (int q = 0; q < 16; q++) { px[q] = 0.f; py[q] = 0.f; }
    #pragma unroll
    for (int q = 0; q < 4; q++) { px[q] = c1[2*q]; py[q] = c1[2*q+1]; }
    int nv = 4;
    for (int e = 0; e < 4; e++) {
        float p1x = c2[2*e], p1y = c2[2*e+1];
        int e2 = (e + 1) & 3;
        float ex = c2[2*e2]   - p1x;
        float ey = c2[2*e2+1] - p1y;
        float d[16];
        #pragma unroll
        for (int q = 0; q < 16; q++) d[q] = ex*(py[q]-p1y) - ey*(px[q]-p1x);
        float ox[16], oy[16];
        #pragma unroll
        for (int q = 0; q < 16; q++) { ox[q] = 0.f; oy[q] = 0.f; }
        int m = 0;
        for (int ii = 0; ii < 8; ii++) {
            int jj = (ii == nv-1) ? 0 : ii+1;
            float dc = d[ii], dn = d[jj];
            float denom = dc - dn;
            if (fabsf(denom) < 1e-8f) denom = 1e-8f;
            float tp = dc / denom;
            float ipx = px[ii] + tp*(px[jj]-px[ii]);
            float ipy = py[ii] + tp*(py[jj]-py[ii]);
            bool act = ii < nv;
            if (act && dc >= 0.f)                    { ox[m] = px[ii]; oy[m] = py[ii]; m++; }
            if (act && ((dc >= 0.f) != (dn >= 0.f))) { ox[m] = ipx;   oy[m] = ipy;   m++; }
        }
        #pragma unroll
        for (int q = 0; q < 16; q++) { px[q] = ox[q]; py[q] = oy[q]; }
        nv = m;
    }
    float s = 0.f;
    for (int ii = 0; ii < 16; ii++) {
        int jj = (ii == nv-1) ? 0 : ii+1;
        if (jj > 15) jj = 15;                 // jax gather clamp
        if (ii < nv) s += px[ii]*py[jj] - px[jj]*py[ii];
    }
    return 0.5f*fabsf(s);
}

// ---------------- K4: suppression bits, circle-method, 1 pair/thread, packed loads ----------------
// Pair {a, (a+d)%TOPK}, d in [1,TOPK/2] covers all unordered pairs (d=TOPK/2
// twice; atomicOr idempotent). pack[a] (broadcast) and pack[j] (coalesced) are
// independent loads -> ~1 exposed latency per thread, 1252 blocks keep occ high.
__global__ void __launch_bounds__(256) kIoU() {
    int n = blockIdx.y;
    int t = blockIdx.x*256 + threadIdx.x;
    if (t >= TOPK*(TOPK/2)) return;
    int a = t / (TOPK/2);
    int d = (t % (TOPK/2)) + 1;
    int j = a + d; if (j >= TOPK) j -= TOPK;
    const float4* pk = g_pack + n*TOPK;
    float4 pa = pk[a];           // broadcast within warp
    float4 pb = pk[j];           // coalesced; independent of pa
    if (pa.w == 0.f || pb.w != pa.w) return;
    float ddx = pa.x - pb.x, ddy = pa.y - pb.y;
    float rr = pa.z + pb.z;
    if (ddx*ddx + ddy*ddy > rr*rr) return;    // conservative no-overlap reject
    int i  = (a < j) ? a : j;
    int jx = (a < j) ? j : a;
    float4 mi = g_meta[n*TOPK + i];
    float4 mj = g_meta[n*TOPK + jx];
    const float* ci = g_corners + ((size_t)n*TOPK + i)*8;
    const float* cj = g_corners + ((size_t)n*TOPK + jx)*8;
    float c1[8], c2[8];
    #pragma unroll
    for (int q = 0; q < 8; q++) { c1[q] = ci[q]; c2[q] = cj[q]; }
    float inter = quad_inter_area(c1, c2);
    float iou = inter / (mi.w + mj.w - inter + 1e-7f);
    if (iou > 0.4f)
        atomicOr(&g_sup[(size_t)n*TOPK*NWORDS + i*NWORDS + (jx >> 5)], 1u << (jx & 31));
}

// ---------------- K5: greedy NMS (sparse rows) + output + g_sup reset ----------------
__global__ void __launch_bounds__(512) kNmsOut(float* __restrict__ out) {
    int n = blockIdx.x;
    int tid = threadIdx.x;   // 512 threads
    __shared__ unsigned int  s_sup[TOPK*NWORDS];
    __shared__ unsigned int  s_keep[NWORDS];
    __shared__ int           s_list[TOPK];
    __shared__ int           s_R;
    __shared__ unsigned char s_rowAny[TOPK];
    __shared__ int           s_wpref[NWORDS+1];

    for (int idx = tid; idx < TOPK*NWORDS; idx += blockDim.x) {
        s_sup[idx] = g_sup[(size_t)n*TOPK*NWORDS + idx];
        g_sup[(size_t)n*TOPK*NWORDS + idx] = 0u;   // reset for next graph replay
    }
    {
        int j = tid;
        int flag = (j < TOPK) ? (g_label[n*TOPK + j] != 0) : 0;
        unsigned int bal = __ballot_sync(0xffffffffu, flag != 0);
        if ((tid & 31) == 0 && (tid >> 5) < NWORDS) s_keep[tid >> 5] = bal;
    }
    __syncthreads();
    if (tid < TOPK) {
        unsigned int any = 0;
        #pragma unroll
        for (int w = 0; w < NWORDS; w++) any |= s_sup[tid*NWORDS + w];
        s_rowAny[tid] = any ? 1 : 0;
    }
    __syncthreads();
    if (tid < 32) {
        int cnt = 0;
        for (int g = 0; g < NWORDS; g++) {
            int i = g*32 + tid;
            int f = (i < TOPK) ? (int)s_rowAny[i] : 0;
            unsigned int bal = __ballot_sync(0xffffffffu, f);
            if (f) s_list[cnt + __popc(bal & ((1u << tid) - 1u))] = i;
            cnt += __popc(bal);
        }
        if (tid == 0) s_R = cnt;
        __syncwarp();
        unsigned int kw = (tid < NWORDS) ? s_keep[tid] : 0u;
        int R = s_R;
        for (int r = 0; r < R; r++) {
            int i = s_list[r];
            unsigned int ow = __shfl_sync(0xffffffffu, kw, i >> 5);
            if ((ow >> (i & 31)) & 1u) {
                if (tid < NWORDS) kw &= ~s_sup[i*NWORDS + tid];
            }
        }
        if (tid < NWORDS) s_keep[tid] = kw;
    }
    __syncthreads();
    if (tid == 0) {
        int acc = 0;
        for (int w = 0; w < NWORDS; w++) { s_wpref[w] = acc; acc += __popc(s_keep[w]); }
        s_wpref[NWORDS] = acc;
    }
    __syncthreads();
    int kcount = s_wpref[NWORDS]; if (kcount > POSTN) kcount = POSTN;
    if (tid < TOPK) {
        int j = tid;
        unsigned int w = s_keep[j >> 5];
        if ((w >> (j & 31)) & 1u) {
            int rank = s_wpref[j >> 5] + __popc(w & ((1u << (j & 31)) - 1u));
            if (rank < POSTN) {
                float* row = out + ((size_t)n*POSTN + rank)*11;
                const float* c = g_corners + ((size_t)n*TOPK + j)*8;
                #pragma unroll
                for (int q = 0; q < 8; q++) row[q] = c[q];
                row[8]  = g_score[n*TOPK + j];
                row[9]  = (float)g_label[n*TOPK + j];
                row[10] = 1.0f;
            }
        }
    }
    for (int idx = tid; idx < (POSTN - kcount)*11; idx += blockDim.x)
        out[((size_t)n*POSTN + kcount)*11 + idx] = 0.0f;
}

// ---------------- launch ----------------
extern "C" void kernel_launch(void* const* d_in, const int* in_sizes, int n_in,
                              void* d_out, int out_size) {
    const float* box_cls = (const float*)d_in[0];
    const float* box_reg = (const float*)d_in[1];
    const float* ctr     = (const float*)d_in[2];
    const float* angle   = (const float*)d_in[3];
    const float* anchors = (const float*)d_in[4];
    float* out = (float*)d_out;
    (void)in_sizes; (void)n_in; (void)out_size;

    cudaFuncSetAttribute(kFilterSort, cudaFuncAttributeMaxDynamicSharedMemorySize, CAP*8);

    kPass      <<<dim3(240, NIMG), 256>>>(box_cls, ctr);
    kFilterSort<<<NIMG, 1024, CAP*8>>>();
    kDecode    <<<dim3(100, NIMG), 256>>>(angle, box_reg, anchors);
    kIoU       <<<dim3((TOPK*(TOPK/2) + 255)/256, NIMG), 256>>>();
    kNmsOut    <<<NIMG, 512>>>(out);
}

// round 15
// speedup vs baseline: 1.2000x; 1.2000x over previous
#include <cuda_runtime.h>
#include <math.h>

#define NIMG 4
#define CC 15
#define KLOC 65536            // H*W
#define KC (KLOC*CC)          // 983040
#define TOPK 400
#define POSTN 100
#define NBINS 2048            // fine bins over [0.25, 1): (bits-FLOOR)>>13
#define BIN_SHIFT 13
#define CAP 16384
#define SPILLCAP 262144
#define NWORDS 13             // ceil(400/32)
#define FLOOR_BITS 0x3E800000u    // 0.25f
#define SCREEN_SUM (-1e-3f)       // x+y >= 0 is necessary for sig(x)*sig(y) >= 0.25

// ---------------- scratch (device globals; zero-initialized at load; kernels
// restore them to zero each iteration, so graph replays are deterministic) ----
__device__ unsigned int       g_hist[NIMG*NBINS];
__device__ int                g_scnt[NIMG];
__device__ unsigned long long g_spill[(size_t)NIMG*SPILLCAP];
__device__ unsigned long long g_top[NIMG*TOPK];
__device__ float              g_corners[NIMG*TOPK*8];
__device__ float4             g_meta[NIMG*TOPK];     // cx, cy, radius, area
__device__ float4             g_pack[NIMG*TOPK];     // cx, cy, radius, label (0 = invalid)
__device__ float              g_score[NIMG*TOPK];
__device__ int                g_label[NIMG*TOPK];    // 0 when invalid
__device__ unsigned int       g_sup[NIMG*TOPK*NWORDS];

__device__ __forceinline__ float sigmoidf_(float x){ return 1.0f/(1.0f+expf(-x)); }

// ---------------- K1: single pass over box_cls (AM-GM sum screen, no ballots) ----------------
__global__ void __launch_bounds__(256) kPass(const float* __restrict__ cls,
                                             const float* __restrict__ ctr) {
    __shared__ unsigned int       sh[NBINS];        // 8 KB
    __shared__ unsigned long long s_buf[4096];      // 32 KB (worst-case = block capacity)
    __shared__ int s_cnt, s_base;
    for (int i = threadIdx.x; i < NBINS; i += blockDim.x) sh[i] = 0u;
    if (threadIdx.x == 0) s_cnt = 0;
    __syncthreads();
    int n = blockIdx.y;
    const float4* base = (const float4*)(cls + (size_t)n*KC);
    const float*  ctrb = ctr + n*KLOC;        // raw logits; L2-hot (reused 15x)
    int v0 = blockIdx.x*1024 + threadIdx.x;   // float4 index within image
    #pragma unroll
    for (int q = 0; q < 4; q++) {
        int v = v0 + q*256;
        float4 x4 = base[v];
        int e = v*4;
        int loc = e & (KLOC-1);
        int c   = e >> 16;                    // class index (4096-elem blocks never straddle)
        float4 y4 = *(const float4*)(ctrb + loc);
        float xs[4] = {x4.x, x4.y, x4.z, x4.w};
        float ys[4] = {y4.x, y4.y, y4.z, y4.w};
        #pragma unroll
        for (int j = 0; j < 4; j++) {
            // AM-GM: sig(x)*sig(y) >= 1/4  =>  x + y >= 0. Pure FADD+FCMP screen.
            if (xs[j] + ys[j] > SCREEN_SUM) {     // ~8% pass
                float comb = sigmoidf_(xs[j]) * sigmoidf_(ys[j]);
                unsigned int b = __float_as_uint(comb);
                if (b >= FLOOR_BITS) {            // exact verify (~4%)
                    atomicAdd(&sh[(b - FLOOR_BITS) >> BIN_SHIFT], 1u);
                    unsigned int flat = (unsigned int)(loc + j)*CC + (unsigned int)c;
                    int p = atomicAdd(&s_cnt, 1); // direct smem append
                    s_buf[p] = ((unsigned long long)b << 32) |
                               (unsigned long long)(0xFFFFFFFFu - flat);
                }
            }
        }
    }
    __syncthreads();
    for (int i = threadIdx.x; i < NBINS; i += blockDim.x)
        if (sh[i]) atomicAdd(&g_hist[n*NBINS + i], sh[i]);
    int cnt = s_cnt;
    if (threadIdx.x == 0 && cnt) s_base = atomicAdd(&g_scnt[n], cnt);
    __syncthreads();
    if (cnt) {
        int b0 = s_base;
        for (int i = threadIdx.x; i < cnt; i += blockDim.x) {
            int p = b0 + i;
            if (p < SPILLCAP) g_spill[(size_t)n*SPILLCAP + p] = s_buf[i];
        }
    }
}

// ---------------- K2: threshold bin (parallel), filter spill, bitonic sort, reset state ----------------
extern __shared__ unsigned long long s_keys[];
__global__ void __launch_bounds__(1024) kFilterSort() {
    __shared__ unsigned int s_gsum[64];
    __shared__ unsigned int s_thr;
    __shared__ int s_sel;
    int n = blockIdx.x, tid = threadIdx.x;    // 1024 threads
    int wid = tid >> 5, lane = tid & 31;

    if (wid < 32) {
        #pragma unroll
        for (int gi = 0; gi < 2; gi++) {
            int g = wid*2 + gi;
            unsigned int v = g_hist[n*NBINS + g*32 + lane];
            #pragma unroll
            for (int off = 16; off; off >>= 1) v += __shfl_xor_sync(0xffffffffu, v, off);
            if (lane == 0) s_gsum[g] = v;
        }
    }
    __syncthreads();
    if (tid == 0) {
        unsigned int run = 0, thr = FLOOR_BITS;
        int tg = -1;
        for (int g = 63; g >= 0; g--) {
            if (run + s_gsum[g] >= TOPK) { tg = g; break; }
            run += s_gsum[g];
        }
        if (tg >= 0) {
            for (int b = tg*32 + 31; b >= tg*32; b--) {
                run += g_hist[n*NBINS + b];
                if (run >= TOPK) { thr = FLOOR_BITS + ((unsigned int)b << BIN_SHIFT); break; }
            }
        }
        s_thr = thr; s_sel = 0;
    }
    __syncthreads();
    unsigned int thr = s_thr;
    int cnt = g_scnt[n]; if (cnt > SPILLCAP) cnt = SPILLCAP;
    const unsigned long long* sp = g_spill + (size_t)n*SPILLCAP;
    for (int i = tid; i < cnt; i += blockDim.x) {
        unsigned long long k = sp[i];
        if ((unsigned int)(k >> 32) >= thr) {   // ~450 passers: direct atomic append
            int p = atomicAdd(&s_sel, 1);
            if (p < CAP) s_keys[p] = k;
        }
    }
    __syncthreads();
    // reset per-image state for the next graph replay (reads above are done)
    for (int i = tid; i < NBINS; i += blockDim.x) g_hist[n*NBINS + i] = 0u;
    if (tid == 0) g_scnt[n] = 0;

    int sel = s_sel; if (sel > CAP) sel = CAP;
    int m = 512;
    while (m < sel) m <<= 1;
    for (int i = tid; i < m; i += blockDim.x)
        if (i >= sel) s_keys[i] = 0ull;
    __syncthreads();
    for (int k = 2; k <= m; k <<= 1) {
        for (int jj = k >> 1; jj > 0; jj >>= 1) {
            for (int i = tid; i < m; i += blockDim.x) {
                int l = i ^ jj;
                if (l > i) {
                    unsigned long long a = s_keys[i], b = s_keys[l];
                    bool desc = ((i & k) == 0);
                    if (desc ? (a < b) : (a > b)) { s_keys[i] = b; s_keys[l] = a; }
                }
            }
            __syncthreads();
        }
    }
    for (int i = tid; i < TOPK; i += blockDim.x)
        g_top[n*TOPK + i] = s_keys[i];   // m >= 512 > TOPK always
}

// ---------------- K3: decode boxes (ONE candidate per 96-thread block; 1600 blocks) ----------------
__global__ void __launch_bounds__(96) kDecode(const float* __restrict__ angle,
                        const float* __restrict__ reg,
                        const float* __restrict__ anchors) {
    __shared__ float s_v[3];
    __shared__ int   s_i[3];
    int n = blockIdx.y;
    int j = blockIdx.x;                    // candidate index [0,400)
    int st = threadIdx.x;                  // 0..95
    int wid = st >> 5, lane = st & 31;
    unsigned long long key = g_top[n*TOPK + j];
    unsigned int bits = (unsigned int)(key >> 32);
    float topv = __uint_as_float(bits);
    bool valid = topv > 0.0f;
    unsigned int flat = 0xFFFFFFFFu - (unsigned int)(key & 0xFFFFFFFFull);
    int loc = valid ? (int)(flat / CC) : 0;
    int cls = valid ? (int)(flat % CC) : 0;

    float bv = -3.402823466e38f; int bi = 1 << 20;
    if (valid && st < 90) {
        bv = __ldg(angle + (size_t)n*90*KLOC + (size_t)st*KLOC + loc);
        bi = st;
    }
    #pragma unroll
    for (int off = 16; off; off >>= 1) {
        float ov = __shfl_xor_sync(0xffffffffu, bv, off);
        int   oi = __shfl_xor_sync(0xffffffffu, bi, off);
        if (ov > bv || (ov == bv && oi < bi)) { bv = ov; bi = oi; }
    }
    if (lane == 0) { s_v[wid] = bv; s_i[wid] = bi; }
    __syncthreads();

    if (st == 0) {
        float v0 = s_v[0]; int i0 = s_i[0];
        #pragma unroll
        for (int w = 1; w < 3; w++) {
            float vw = s_v[w]; int iw = s_i[w];
            if (vw > v0 || (vw == v0 && iw < i0)) { v0 = vw; i0 = iw; }
        }
        int base = n*TOPK + j;
        if (!valid) {
            g_label[base] = 0; g_score[base] = 0.f;
            g_meta[base] = make_float4(0.f, 0.f, 0.f, 0.f);
            g_pack[base] = make_float4(0.f, 0.f, 0.f, 0.f);
            #pragma unroll
            for (int q = 0; q < 8; q++) g_corners[base*8 + q] = 0.f;
            return;
        }
        const float* rp = reg + (size_t)n*4*KLOC + loc;
        float r0 = rp[0], r1 = rp[KLOC], r2 = rp[2*(size_t)KLOC], r3 = rp[3*(size_t)KLOC];
        const float* ap2 = anchors + ((size_t)n*KLOC + loc)*5;
        float acx = ap2[0], acy = ap2[1], aw = ap2[2], ah = ap2[3];
        float dx = r0/10.0f, dy = r1/10.0f;
        float dw = fminf(fmaxf(r2/5.0f, -10.0f), 4.0f);
        float dh = fminf(fmaxf(r3/5.0f, -10.0f), 4.0f);
        float cx = dx*aw + acx, cy = dy*ah + acy;
        float pw = aw*expf(dw), ph = ah*expf(dh);
        bool v2ok = (pw >= 0.0f) && (ph >= 0.0f);
        float ang = (float)i0 - 90.0f;
        float t = ang * 0.017453292519943295f;
        float c = cosf(t), s = sinf(t);
        const float oxm[4] = {1.f,-1.f,-1.f,1.f};
        const float oym[4] = {1.f, 1.f,-1.f,-1.f};
        #pragma unroll
        for (int q = 0; q < 4; q++) {
            float ox = oxm[q]*(pw*0.5f), oy = oym[q]*(ph*0.5f);
            g_corners[base*8 + 2*q]     = cx + ox*c - oy*s;
            g_corners[base*8 + 2*q + 1] = cy + ox*s + oy*c;
        }
        float rad = 0.5f*sqrtf(pw*pw + ph*ph) + 1.0f;
        int   lb  = v2ok ? (cls + 1) : 0;
        g_meta[base]  = make_float4(cx, cy, rad, pw*ph);
        g_pack[base]  = make_float4(cx, cy, rad, (float)lb);
        g_score[base] = v2ok ? sqrtf(fmaxf(topv, 0.f)) : 0.f;
        g_label[base] = lb;                             // 0 encodes invalid
    }
}

// ---------------- rotated quad intersection (mirrors reference Sutherland-Hodgman) ----------------
__device__ float quad_inter_area(const float* c1, const float* c2) {
    float px[16], py[16];
    #pragma unroll
    for (int q = 0; q < 16; q++) { px[q] = 0.f; py[q] = 0.f; }
    #pragma unroll
    for (int q = 0; q < 4; q++) { px[q] = c1[2*q]; py[q] = c1[2*q+1]; }
    int nv = 4;
    for (int e = 0; e < 4; e++) {
        float p1x = c2[2*e], p1y = c2[2*e+1];
        int e2 = (e + 1) & 3;
        float ex = c2[2*e2]   - p1x;
        float ey = c2[2*e2+1] - p1y;
        float d[16];
        #pragma unroll
        for (int q = 0; q < 16; q++) d[q] = ex*(py[q]-p1y) - ey*(px[q]-p1x);
        float ox[16], oy[16];
        #pragma unroll
        for (int q = 0; q < 16; q++) { ox[q] = 0.f; oy[q] = 0.f; }
        int m = 0;
        for (int ii = 0; ii < 8; ii++) {
            int jj = (ii == nv-1) ? 0 : ii+1;
            float dc = d[ii], dn = d[jj];
            float denom = dc - dn;
            if (fabsf(denom) < 1e-8f) denom = 1e-8f;
            float tp = dc / denom;
            float ipx = px[ii] + tp*(px[jj]-px[ii]);
            float ipy = py[ii] + tp*(py[jj]-py[ii]);
            bool act = ii < nv;
            if (act && dc >= 0.f)                    { ox[m] = px[ii]; oy[m] = py[ii]; m++; }
            if (act && ((dc >= 0.f) != (dn >= 0.f))) { ox[m] = ipx;   oy[m] = ipy;   m++; }
        }
        #pragma unroll
        for (int q = 0; q < 16; q++) { px[q] = ox[q]; py[q] = oy[q]; }
        nv = m;
    }
    float s = 0.f;
    for (int ii = 0; ii < 16; ii++) {
        int jj = (ii == nv-1) ? 0 : ii+1;
        if (jj > 15) jj = 15;                 // jax gather clamp
        if (ii < nv) s += px[ii]*py[jj] - px[jj]*py[ii];
    }
    return 0.5f*fabsf(s);
}

// ---------------- K4: suppression bits, circle-method, 1 pair/thread, packed loads ----------------
__global__ void __launch_bounds__(256) kIoU() {
    int n = blockIdx.y;
    int t = blockIdx.x*256 + threadIdx.x;
    if (t >= TOPK*(TOPK/2)) return;
    int a = t / (TOPK/2);
    int d = (t % (TOPK/2)) + 1;
    int j = a + d; if (j >= TOPK) j -= TOPK;
    const float4* pk = g_pack + n*TOPK;
    float4 pa = pk[a];           // broadcast within warp
    float4 pb = pk[j];           // coalesced; independent of pa
    if (pa.w == 0.f || pb.w != pa.w) return;
    float ddx = pa.x - pb.x, ddy = pa.y - pb.y;
    float rr = pa.z + pb.z;
    if (ddx*ddx + ddy*ddy > rr*rr) return;    // conservative no-overlap reject
    int i  = (a < j) ? a : j;
    int jx = (a < j) ? j : a;
    float4 mi = g_meta[n*TOPK + i];
    float4 mj = g_meta[n*TOPK + jx];
    const float* ci = g_corners + ((size_t)n*TOPK + i)*8;
    const float* cj = g_corners + ((size_t)n*TOPK + jx)*8;
    float c1[8], c2[8];
    #pragma unroll
    for (int q = 0; q < 8; q++) { c1[q] = ci[q]; c2[q] = cj[q]; }
    float inter = quad_inter_area(c1, c2);
    float iou = inter / (mi.w + mj.w - inter + 1e-7f);
    if (iou > 0.4f)
        atomicOr(&g_sup[(size_t)n*TOPK*NWORDS + i*NWORDS + (jx >> 5)], 1u << (jx & 31));
}

// ---------------- K5: greedy NMS (sparse rows) + output + g_sup reset ----------------
__global__ void __launch_bounds__(512) kNmsOut(float* __restrict__ out) {
    int n = blockIdx.x;
    int tid = threadIdx.x;   // 512 threads
    __shared__ unsigned int  s_sup[TOPK*NWORDS];
    __shared__ unsigned int  s_keep[NWORDS];
    __shared__ int           s_list[TOPK];
    __shared__ int           s_R;
    __shared__ unsigned char s_rowAny[TOPK];
    __shared__ int           s_wpref[NWORDS+1];

    for (int idx = tid; idx < TOPK*NWORDS; idx += blockDim.x) {
        s_sup[idx] = g_sup[(size_t)n*TOPK*NWORDS + idx];
        g_sup[(size_t)n*TOPK*NWORDS + idx] = 0u;   // reset for next graph replay
    }
    {
        int j = tid;
        int flag = (j < TOPK) ? (g_label[n*TOPK + j] != 0) : 0;
        unsigned int bal = __ballot_sync(0xffffffffu, flag != 0);
        if ((tid & 31) == 0 && (tid >> 5) < NWORDS) s_keep[tid >> 5] = bal;
    }
    __syncthreads();
    if (tid < TOPK) {
        unsigned int any = 0;
        #pragma unroll
        for (int w = 0; w < NWORDS; w++) any |= s_sup[tid*NWORDS + w];
        s_rowAny[tid] = any ? 1 : 0;
    }
    __syncthreads();
    if (tid < 32) {
        int cnt = 0;
        for (int g = 0; g < NWORDS; g++) {
            int i = g*32 + tid;
            int f = (i < TOPK) ? (int)s_rowAny[i] : 0;
            unsigned int bal = __ballot_sync(0xffffffffu, f);
            if (f) s_list[cnt + __popc(bal & ((1u << tid) - 1u))] = i;
            cnt += __popc(bal);
        }
        if (tid == 0) s_R = cnt;
        __syncwarp();
        unsigned int kw = (tid < NWORDS) ? s_keep[tid] : 0u;
        int R = s_R;
        for (int r = 0; r < R; r++) {
            int i = s_list[r];
            unsigned int ow = __shfl_sync(0xffffffffu, kw, i >> 5);
            if ((ow >> (i & 31)) & 1u) {
                if (tid < NWORDS) kw &= ~s_sup[i*NWORDS + tid];
            }
        }
        if (tid < NWORDS) s_keep[tid] = kw;
    }
    __syncthreads();
    if (tid == 0) {
        int acc = 0;
        for (int w = 0; w < NWORDS; w++) { s_wpref[w] = acc; acc += __popc(s_keep[w]); }
        s_wpref[NWORDS] = acc;
    }
    __syncthreads();
    int kcount = s_wpref[NWORDS]; if (kcount > POSTN) kcount = POSTN;
    if (tid < TOPK) {
        int j = tid;
        unsigned int w = s_keep[j >> 5];
        if ((w >> (j & 31)) & 1u) {
            int rank = s_wpref[j >> 5] + __popc(w & ((1u << (j & 31)) - 1u));
            if (rank < POSTN) {
                float* row = out + ((size_t)n*POSTN + rank)*11;
                const float* c = g_corners + ((size_t)n*TOPK + j)*8;
                #pragma unroll
                for (int q = 0; q < 8; q++) row[q] = c[q];
                row[8]  = g_score[n*TOPK + j];
                row[9]  = (float)g_label[n*TOPK + j];
                row[10] = 1.0f;
            }
        }
    }
    for (int idx = tid; idx < (POSTN - kcount)*11; idx += blockDim.x)
        out[((size_t)n*POSTN + kcount)*11 + idx] = 0.0f;
}

// ---------------- launch ----------------
extern "C" void kernel_launch(void* const* d_in, const int* in_sizes, int n_in,
                              void* d_out, int out_size) {
    const float* box_cls = (const float*)d_in[0];
    const float* box_reg = (const float*)d_in[1];
    const float* ctr     = (const float*)d_in[2];
    const float* angle   = (const float*)d_in[3];
    const float* anchors = (const float*)d_in[4];
    float* out = (float*)d_out;
    (void)in_sizes; (void)n_in; (void)out_size;

    cudaFuncSetAttribute(kFilterSort, cudaFuncAttributeMaxDynamicSharedMemorySize, CAP*8);

    kPass      <<<dim3(240, NIMG), 256>>>(box_cls, ctr);
    kFilterSort<<<NIMG, 1024, CAP*8>>>();
    kDecode    <<<dim3(TOPK, NIMG), 96>>>(angle, box_reg, anchors);
    kIoU       <<<dim3((TOPK*(TOPK/2) + 255)/256, NIMG), 256>>>();
    kNmsOut    <<<NIMG, 512>>>(out);
}